// round 1
// baseline (speedup 1.0000x reference)
#include <cuda_runtime.h>
#include <cuda_bf16.h>

#define BATCH 16
#define N 256
#define DIM 128

// Scratch (device globals: allocation-free per harness rules)
__device__ float  g_dist[BATCH * N * N];   // 4 MB, fp32 pairwise distances
__device__ double g_bsum[BATCH];           // per-batch matched sums

// ---------------------------------------------------------------------------
// Kernel A: pairwise L2 distances. One block computes a 16x16 tile of dist.
// grid = (16 col-tiles, 16 row-tiles, 16 batches), 256 threads.
// ---------------------------------------------------------------------------
__global__ __launch_bounds__(256) void dist_kernel(const float* __restrict__ pred,
                                                   const float* __restrict__ tgt) {
    __shared__ float sp[16 * 132];   // 16 rows x 128 floats, padded to 132
    __shared__ float st[16 * 132];
    const int b  = blockIdx.z;
    const int rt = blockIdx.y;
    const int ct = blockIdx.x;
    const int tid = threadIdx.x;

    const float4* p4 = (const float4*)(pred + (size_t)(b * N + rt * 16) * DIM);
    const float4* t4 = (const float4*)(tgt  + (size_t)(b * N + ct * 16) * DIM);
    for (int idx = tid; idx < 512; idx += 256) {     // 16*128/4 = 512 float4
        int r = idx >> 5, c = idx & 31;
        *(float4*)&sp[r * 132 + c * 4] = p4[idx];
        *(float4*)&st[r * 132 + c * 4] = t4[idx];
    }
    __syncthreads();

    const int ti = tid >> 4;   // 0..15 row within tile
    const int tj = tid & 15;   // 0..15 col within tile
    float acc = 0.f;
#pragma unroll
    for (int d4 = 0; d4 < 32; ++d4) {
        float4 a = *(const float4*)&sp[ti * 132 + d4 * 4];
        float4 c = *(const float4*)&st[tj * 132 + d4 * 4];
        float dx = a.x - c.x, dy = a.y - c.y, dz = a.z - c.z, dw = a.w - c.w;
        acc += dx * dx + dy * dy + dz * dz + dw * dw;
    }
    g_dist[((size_t)b << 16) + (size_t)(rt * 16 + ti) * N + (ct * 16 + tj)] = sqrtf(acc);
}

// ---------------------------------------------------------------------------
// Kernel B: per-batch Jonker-Volgenant LSA on u16-quantized costs.
// One block per batch, 256 threads. Phase 1: quantize dist -> smem u16.
// Phase 2 (warp 0 only): Dijkstra with potentials, deferred dual updates.
//   Each lane owns 8 consecutive columns; D/v/used/pi live in registers.
// Phase 3: all threads gather matched fp32 distances, deterministic reduce.
// ---------------------------------------------------------------------------
#define QSCALE 2048.0f
#define INF_D  0x3F000000
#define INF_M  0x7F000000

// dynamic smem layout (bytes)
#define OFF_COST 0                      // u16[65536]           = 131072
#define OFF_U    131072                 // int[257]             = 1028
#define OFF_P    (131072 + 1028)        // u16[257]             = 514
#define OFF_WAY  (131072 + 1028 + 514)  // u16[257]             = 514
#define OFF_SRED (131072 + 1028 + 514 + 514)  // = 133128, 8-aligned; double[8]
#define SMEM_B   (OFF_SRED + 64)

extern __shared__ char s_raw[];

__global__ __launch_bounds__(256) void hungarian_kernel() {
    const int b   = blockIdx.x;
    const int tid = threadIdx.x;

    unsigned short* cost = (unsigned short*)(s_raw + OFF_COST);
    int*            u_   = (int*)(s_raw + OFF_U);
    unsigned short* p_   = (unsigned short*)(s_raw + OFF_P);
    unsigned short* way_ = (unsigned short*)(s_raw + OFF_WAY);
    double*         sred = (double*)(s_raw + OFF_SRED);

    // ---- Phase 1: quantize the fp32 distance block into shared u16 ----
    const float4* dsrc = (const float4*)(g_dist + ((size_t)b << 16));
    for (int idx = tid; idx < (N * N) / 4; idx += 256) {
        float4 d = dsrc[idx];
        int q0 = __float2int_rn(d.x * QSCALE); q0 = q0 > 65535 ? 65535 : q0;
        int q1 = __float2int_rn(d.y * QSCALE); q1 = q1 > 65535 ? 65535 : q1;
        int q2 = __float2int_rn(d.z * QSCALE); q2 = q2 > 65535 ? 65535 : q2;
        int q3 = __float2int_rn(d.w * QSCALE); q3 = q3 > 65535 ? 65535 : q3;
        ((ushort4*)cost)[idx] = make_ushort4((unsigned short)q0, (unsigned short)q1,
                                             (unsigned short)q2, (unsigned short)q3);
    }
    for (int i = tid; i < N + 1; i += 256) { u_[i] = 0; p_[i] = 0; }
    __syncthreads();

    // ---- Phase 2: warp 0 runs the LSA ----
    if (tid < 32) {
        const unsigned FULL = 0xffffffffu;
        const int lane = tid;
        int vreg[8], Dreg[8], pireg[8];
#pragma unroll
        for (int k = 0; k < 8; ++k) vreg[k] = 0;

        for (int i = 1; i <= N; ++i) {
            unsigned usedmask = 0;
#pragma unroll
            for (int k = 0; k < 8; ++k) Dreg[k] = INF_D;
            if (lane == 0) p_[0] = (unsigned short)i;

            int S = 0;
            int i0 = i;      // current row being relaxed (u[i]=0 for the new row)
            int j0 = 0;      // virtual start column
            int jfinal;

            while (true) {
                const int u0 = u_[i0];
                const uint4 cc = ((const uint4*)(cost + ((i0 - 1) << 8)))[lane];
                unsigned cw[4] = {cc.x, cc.y, cc.z, cc.w};
#pragma unroll
                for (int k = 0; k < 8; ++k) {
                    if (!((usedmask >> k) & 1u)) {
                        int c = (int)((cw[k >> 1] >> ((k & 1) * 16)) & 0xFFFFu);
                        int cand = S + c - u0 - vreg[k];
                        if (cand < Dreg[k]) {
                            Dreg[k] = cand;
                            way_[(lane << 3) + k + 1] = (unsigned short)j0;
                        }
                    }
                }
                // min over free columns
                int mn = INF_M;
#pragma unroll
                for (int k = 0; k < 8; ++k)
                    if (!((usedmask >> k) & 1u) && Dreg[k] < mn) mn = Dreg[k];
                const int g = __reduce_min_sync(FULL, mn);
                // lowest column achieving the min
                int localj = 0x7FFFFFFF;
#pragma unroll
                for (int k = 0; k < 8; ++k)
                    if (localj == 0x7FFFFFFF && !((usedmask >> k) & 1u) && Dreg[k] == g)
                        localj = (lane << 3) + k + 1;
                const unsigned bal = __ballot_sync(FULL, localj != 0x7FFFFFFF);
                const int src = __ffs(bal) - 1;
                const int j1  = __shfl_sync(FULL, localj, src);
                S = g;
                const int pj1 = p_[j1];
                if (pj1 == 0) { jfinal = j1; break; }
                // freeze j1 on its owner lane (static-index predicated loop)
#pragma unroll
                for (int k = 0; k < 8; ++k)
                    if (((lane << 3) + k + 1) == j1) { usedmask |= (1u << k); pireg[k] = pj1; }
                i0 = pj1;
                j0 = j1;
            }

            const int mu = S;
            __syncwarp();                 // way_ writes visible to lane 0
            if (lane == 0) {
                int jj = jfinal;          // augment along the alternating path
                while (jj != 0) {
                    int jp = way_[jj];
                    p_[jj] = p_[jp];
                    jj = jp;
                }
                u_[i] += mu;              // virtual column 0 (D=0)
            }
            // deferred dual updates for columns frozen this round
#pragma unroll
            for (int k = 0; k < 8; ++k)
                if ((usedmask >> k) & 1u) {
                    int adj = mu - Dreg[k];
                    vreg[k] -= adj;
                    u_[pireg[k]] += adj;  // distinct rows: race-free
                }
            __syncwarp();
        }
    }
    __syncthreads();

    // ---- Phase 3: gather matched fp32 distances, deterministic block sum ----
    {
        const int j   = tid + 1;
        const int row = p_[j];
        float val = g_dist[((size_t)b << 16) + (size_t)(row - 1) * N + (j - 1)];
        double d = (double)val;
#pragma unroll
        for (int off = 16; off > 0; off >>= 1)
            d += __shfl_down_sync(0xffffffffu, d, off);
        if ((tid & 31) == 0) sred[tid >> 5] = d;
        __syncthreads();
        if (tid == 0) {
            double t = 0.0;
#pragma unroll
            for (int w = 0; w < 8; ++w) t += sred[w];   // fixed order
            g_bsum[b] = t;
        }
    }
}

// ---------------------------------------------------------------------------
// Kernel C: deterministic final reduce + mean
// ---------------------------------------------------------------------------
__global__ void finalize_kernel(float* __restrict__ out) {
    double t = 0.0;
#pragma unroll
    for (int b = 0; b < BATCH; ++b) t += g_bsum[b];
    out[0] = (float)(t / (double)(BATCH * N));
}

// ---------------------------------------------------------------------------
extern "C" void kernel_launch(void* const* d_in, const int* in_sizes, int n_in,
                              void* d_out, int out_size) {
    const float* pred = (const float*)d_in[0];
    const float* tgt  = (const float*)d_in[1];
    float* out = (float*)d_out;

    cudaFuncSetAttribute(hungarian_kernel,
                         cudaFuncAttributeMaxDynamicSharedMemorySize, SMEM_B);

    dist_kernel<<<dim3(16, 16, 16), 256>>>(pred, tgt);
    hungarian_kernel<<<BATCH, 256, SMEM_B>>>();
    finalize_kernel<<<1, 1>>>(out);
}